// round 8
// baseline (speedup 1.0000x reference)
#include <cuda_runtime.h>
#include <cstdint>

#define MDIM 8192
#define NDIM 4096
#define KDIM 4096

// ---------------- scratch (device globals; no allocation allowed) ----------------
__device__ __align__(16) uint8_t g_Xq[(size_t)MDIM * KDIM]; // 32 MB
__device__ __align__(16) int8_t  g_Wq[(size_t)NDIM * KDIM]; // 16 MB
__device__ float g_sa[MDIM];
__device__ int   g_zp[MDIM];
__device__ float g_sw[NDIM];
__device__ int   g_rws[NDIM];

// ---------------- weight quantization: row-wise symmetric int8 (round-5 proven) ----------------
__global__ void __launch_bounds__(128) quant_w_kernel(const float* __restrict__ w) {
    __shared__ float sm[4];
    __shared__ int   si[4];
    const int n = blockIdx.x, t = threadIdx.x;
    const float4* row = reinterpret_cast<const float4*>(w + (size_t)n * KDIM);
    float4 v[8];
    float am = 0.f;
#pragma unroll
    for (int i = 0; i < 8; i++) {
        v[i] = row[t + i * 128];
        am = fmaxf(am, fmaxf(fmaxf(fabsf(v[i].x), fabsf(v[i].y)),
                             fmaxf(fabsf(v[i].z), fabsf(v[i].w))));
    }
#pragma unroll
    for (int o = 16; o > 0; o >>= 1) am = fmaxf(am, __shfl_xor_sync(0xffffffffu, am, o));
    if ((t & 31) == 0) sm[t >> 5] = am;
    __syncthreads();
    am = fmaxf(fmaxf(sm[0], sm[1]), fmaxf(sm[2], sm[3]));
    const float scale = (am > 0.f) ? (am / 127.0f) : 1.0f;

    char4* out = reinterpret_cast<char4*>(g_Wq + (size_t)n * KDIM);
    int ssum = 0;
#pragma unroll
    for (int i = 0; i < 8; i++) {
        int qx = (int)fminf(fmaxf(rintf(v[i].x / scale), -127.f), 127.f);
        int qy = (int)fminf(fmaxf(rintf(v[i].y / scale), -127.f), 127.f);
        int qz = (int)fminf(fmaxf(rintf(v[i].z / scale), -127.f), 127.f);
        int qw = (int)fminf(fmaxf(rintf(v[i].w / scale), -127.f), 127.f);
        ssum += qx + qy + qz + qw;
        out[t + i * 128] = make_char4((char)qx, (char)qy, (char)qz, (char)qw);
    }
#pragma unroll
    for (int o = 16; o > 0; o >>= 1) ssum += __shfl_xor_sync(0xffffffffu, ssum, o);
    if ((t & 31) == 0) si[t >> 5] = ssum;
    __syncthreads();
    if (t == 0) {
        g_sw[n]  = scale;
        g_rws[n] = si[0] + si[1] + si[2] + si[3];
    }
}

// ---------------- activation quantization: per-token asymmetric uint8 (round-5 proven) ----------------
__global__ void __launch_bounds__(128) quant_x_kernel(const float* __restrict__ x) {
    __shared__ float smn[4], smx[4];
    const int m = blockIdx.x, t = threadIdx.x;
    const float4* row = reinterpret_cast<const float4*>(x + (size_t)m * KDIM);
    float4 v[8];
    float mn = 3.4e38f, mx = -3.4e38f;
#pragma unroll
    for (int i = 0; i < 8; i++) {
        v[i] = row[t + i * 128];
        mn = fminf(mn, fminf(fminf(v[i].x, v[i].y), fminf(v[i].z, v[i].w)));
        mx = fmaxf(mx, fmaxf(fmaxf(v[i].x, v[i].y), fmaxf(v[i].z, v[i].w)));
    }
#pragma unroll
    for (int o = 16; o > 0; o >>= 1) {
        mn = fminf(mn, __shfl_xor_sync(0xffffffffu, mn, o));
        mx = fmaxf(mx, __shfl_xor_sync(0xffffffffu, mx, o));
    }
    if ((t & 31) == 0) { smn[t >> 5] = mn; smx[t >> 5] = mx; }
    __syncthreads();
    mn = fminf(fminf(smn[0], smn[1]), fminf(smn[2], smn[3]));
    mx = fmaxf(fmaxf(smx[0], smx[1]), fmaxf(smx[2], smx[3]));
    const float rng   = mx - mn;
    const float scale = (rng > 0.f) ? (rng / 255.0f) : 1.0f;
    const float zpf   = rintf((-mn) / scale);

    uchar4* out = reinterpret_cast<uchar4*>(g_Xq + (size_t)m * KDIM);
#pragma unroll
    for (int i = 0; i < 8; i++) {
        float qx = fminf(fmaxf(rintf(v[i].x / scale) + zpf, 0.f), 255.f);
        float qy = fminf(fmaxf(rintf(v[i].y / scale) + zpf, 0.f), 255.f);
        float qz = fminf(fmaxf(rintf(v[i].z / scale) + zpf, 0.f), 255.f);
        float qw = fminf(fmaxf(rintf(v[i].w / scale) + zpf, 0.f), 255.f);
        out[t + i * 128] = make_uchar4((unsigned char)qx, (unsigned char)qy,
                                       (unsigned char)qz, (unsigned char)qw);
    }
    if (t == 0) { g_sa[m] = scale; g_zp[m] = (int)zpf; }
}

// ---------------- int8 GEMM: u8 x s8 -> s32, mma.sync m16n8k32 ----------------
// CTA 128x128, BK=128/stage, 3-stage cp.async ring, 4 warps, warp tile 64x64.
#define BM 128
#define BN 128
#define BKB 128
#define NSTG 3
#define NKT (KDIM / BKB)                         // 32 stages
#define STG_BYTES ((BM + BN) * BKB)              // 32768
#define SCALE_OFF (NSTG * STG_BYTES)             // 98304
#define DSMEM_BYTES (SCALE_OFF + 2560 + 1024)    // 101888

#define CP_ASYNC16(dst, src) \
    asm volatile("cp.async.cg.shared.global [%0], [%1], 16;\n" \
                 :: "r"(dst), "l"(__cvta_generic_to_global(src)))

#define LDSM_X4(R0, R1, R2, R3, A) \
    asm volatile("ldmatrix.sync.aligned.m8n8.x4.shared.b16 {%0,%1,%2,%3}, [%4];\n" \
                 : "=r"(R0), "=r"(R1), "=r"(R2), "=r"(R3) : "r"(A))

#define MMA_U8S8(C0, C1, C2, C3, A0, A1, A2, A3, B0, B1)               \
    asm volatile("mma.sync.aligned.m16n8k32.row.col.s32.u8.s8.s32 "    \
                 "{%0,%1,%2,%3}, {%4,%5,%6,%7}, {%8,%9}, {%0,%1,%2,%3};\n" \
                 : "+r"(C0), "+r"(C1), "+r"(C2), "+r"(C3)              \
                 : "r"(A0), "r"(A1), "r"(A2), "r"(A3), "r"(B0), "r"(B1))

extern __shared__ uint8_t dsm_raw[];

__device__ __forceinline__ void load_stage(uint32_t dstA, uint32_t dstB,
                                           const uint8_t* pA, const uint8_t* pB, int ko) {
#pragma unroll
    for (int i = 0; i < 8; i++)
        CP_ASYNC16(dstA + i * 2048, pA + (size_t)i * 16 * KDIM + ko);
#pragma unroll
    for (int i = 0; i < 8; i++)
        CP_ASYNC16(dstB + i * 2048, pB + (size_t)i * 16 * KDIM + ko);
    asm volatile("cp.async.commit_group;\n" ::: "memory");
}

__global__ void __launch_bounds__(128, 2) gemm_kernel(const float* __restrict__ bias,
                                                      float* __restrict__ out) {
    const int t    = threadIdx.x;
    const int warp = t >> 5, lane = t & 31;
    const int m0   = blockIdx.y * BM;
    const int n0   = blockIdx.x * BN;

    const uint32_t raw   = (uint32_t)__cvta_generic_to_shared(dsm_raw);
    const uint32_t sbase = (raw + 1023u) & ~1023u;
    uint8_t* sb_g = dsm_raw + (sbase - raw);

    float* sSa   = (float*)(sb_g + SCALE_OFF);
    int*   sZp   = (int*)  (sb_g + SCALE_OFF + 512);
    float* sSw   = (float*)(sb_g + SCALE_OFF + 1024);
    int*   sRw   = (int*)  (sb_g + SCALE_OFF + 1536);
    float* sBias = (float*)(sb_g + SCALE_OFF + 2048);

    sSa[t]   = g_sa[m0 + t];
    sZp[t]   = g_zp[m0 + t];
    sSw[t]   = g_sw[n0 + t];
    sRw[t]   = g_rws[n0 + t];
    sBias[t] = bias[n0 + t];

    // ---- loader mapping: thread handles rows {16i + tr}, 16B chunk c, fixed swizzle ----
    const int tr = t >> 3, c = t & 7;                 // tr in 0..15, c in 0..7
    const uint32_t swc = (uint32_t)((c ^ (tr & 7)) << 4);
    const uint8_t* pA = g_Xq + (size_t)(m0 + tr) * KDIM + c * 16;
    const uint8_t* pB = (const uint8_t*)g_Wq + (size_t)(n0 + tr) * KDIM + c * 16;
    const uint32_t ldA = tr * BKB + swc;              // offset within stage A region
    const uint32_t ldB = BM * BKB + tr * BKB + swc;   // offset within stage B region

    // ---- fragment addressing ----
    const int wm = warp >> 1, wn = warp & 1;          // warp tile 64x64
    const int aRow = wm * 64 + (lane & 15);
    const int aCh  = (lane >> 4) & 1;
    const int bRow = wn * 64 + (lane & 7) + ((lane >> 4) & 1) * 8;
    const int bCh  = (lane >> 3) & 1;
    const int l7   = lane & 7;                        // (row & 7) for both A and B frag rows

    int acc[4][8][4];
#pragma unroll
    for (int mi = 0; mi < 4; mi++)
#pragma unroll
        for (int ni = 0; ni < 8; ni++)
#pragma unroll
            for (int r = 0; r < 4; r++) acc[mi][ni][r] = 0;

    // prologue: stages 0,1
    load_stage(sbase + 0 * STG_BYTES + ldA, sbase + 0 * STG_BYTES + ldB, pA, pB, 0);
    load_stage(sbase + 1 * STG_BYTES + ldA, sbase + 1 * STG_BYTES + ldB, pA, pB, BKB);

    int slot = 0, lslot = 2;
#pragma unroll 1
    for (int stg = 0; stg < NKT; stg++) {
        if (stg + 2 < NKT) {
            load_stage(sbase + lslot * STG_BYTES + ldA, sbase + lslot * STG_BYTES + ldB,
                       pA, pB, (stg + 2) * BKB);
            lslot++; if (lslot == NSTG) lslot = 0;
        } else {
            asm volatile("cp.async.commit_group;\n" ::: "memory");
        }
        asm volatile("cp.async.wait_group 2;\n" ::: "memory");
        __syncthreads();

        const uint32_t sa = sbase + slot * STG_BYTES;
        const uint32_t sb = sa + BM * BKB;
#pragma unroll
        for (int ks = 0; ks < 4; ks++) {
            uint32_t a[4][4], bq[4][4];
            const uint32_t achu = (uint32_t)(((ks * 2 + aCh) ^ l7) << 4);
            const uint32_t bchu = (uint32_t)(((ks * 2 + bCh) ^ l7) << 4);
#pragma unroll
            for (int mi = 0; mi < 4; mi++) {
                const uint32_t ad = sa + (uint32_t)(aRow + mi * 16) * BKB + achu;
                LDSM_X4(a[mi][0], a[mi][1], a[mi][2], a[mi][3], ad);
            }
#pragma unroll
            for (int nj = 0; nj < 4; nj++) {
                const uint32_t ad = sb + (uint32_t)(bRow + nj * 16) * BKB + bchu;
                LDSM_X4(bq[nj][0], bq[nj][1], bq[nj][2], bq[nj][3], ad);
            }
#pragma unroll
            for (int mi = 0; mi < 4; mi++)
#pragma unroll
                for (int ni = 0; ni < 8; ni++) {
                    MMA_U8S8(acc[mi][ni][0], acc[mi][ni][1], acc[mi][ni][2], acc[mi][ni][3],
                             a[mi][0], a[mi][1], a[mi][2], a[mi][3],
                             bq[ni >> 1][(ni & 1) * 2], bq[ni >> 1][(ni & 1) * 2 + 1]);
                }
        }
        __syncthreads();
        slot++; if (slot == NSTG) slot = 0;
    }

    // ---- epilogue: zero-point correction (exact int32) + dequant + bias ----
    const int rBase = wm * 64 + (lane >> 2);
    const int cBase = wn * 64 + (lane & 3) * 2;
#pragma unroll
    for (int mi = 0; mi < 4; mi++) {
        const int r0 = rBase + mi * 16;
        const int r1 = r0 + 8;
        const float sa0 = sSa[r0], sa1 = sSa[r1];
        const int   zp0 = sZp[r0], zp1 = sZp[r1];
        float* o0 = out + (size_t)(m0 + r0) * NDIM + n0;
        float* o1 = out + (size_t)(m0 + r1) * NDIM + n0;
#pragma unroll
        for (int ni = 0; ni < 8; ni++) {
            const int cc = cBase + ni * 8;
            const float sw0 = sSw[cc], sw1 = sSw[cc + 1];
            const int   rw0 = sRw[cc], rw1 = sRw[cc + 1];
            const float bb0 = sBias[cc], bb1 = sBias[cc + 1];
            float2 y0, y1;
            y0.x = (float)(acc[mi][ni][0] - zp0 * rw0) * (sa0 * sw0) + bb0;
            y0.y = (float)(acc[mi][ni][1] - zp0 * rw1) * (sa0 * sw1) + bb1;
            y1.x = (float)(acc[mi][ni][2] - zp1 * rw0) * (sa1 * sw0) + bb0;
            y1.y = (float)(acc[mi][ni][3] - zp1 * rw1) * (sa1 * sw1) + bb1;
            *reinterpret_cast<float2*>(o0 + cc) = y0;
            *reinterpret_cast<float2*>(o1 + cc) = y1;
        }
    }
}

// ---------------- launch ----------------
extern "C" void kernel_launch(void* const* d_in, const int* in_sizes, int n_in,
                              void* d_out, int out_size) {
    (void)in_sizes; (void)n_in; (void)out_size;
    const float* x    = (const float*)d_in[0];
    const float* w    = (const float*)d_in[1];
    const float* bias = (const float*)d_in[2];
    float* out = (float*)d_out;

    cudaFuncSetAttribute(gemm_kernel,
                         cudaFuncAttributeMaxDynamicSharedMemorySize, DSMEM_BYTES);

    quant_w_kernel<<<NDIM, 128>>>(w);
    quant_x_kernel<<<MDIM, 128>>>(x);
    dim3 grid(NDIM / BN, MDIM / BM);
    gemm_kernel<<<grid, 128, DSMEM_BYTES>>>(bias, out);
}

// round 9
// speedup vs baseline: 1.0027x; 1.0027x over previous
#include <cuda_runtime.h>
#include <cstdint>

#define MDIM 8192
#define NDIM 4096
#define KDIM 4096

// ---------------- scratch (device globals; no allocation allowed) ----------------
__device__ __align__(16) int8_t g_Xq[(size_t)MDIM * KDIM]; // 32 MB, stores (Xq - 128) as s8
__device__ __align__(16) int8_t g_Wq[(size_t)NDIM * KDIM]; // 16 MB
__device__ float g_sa[MDIM];
__device__ int   g_zp[MDIM];
__device__ float g_sw[NDIM];
__device__ int   g_rws[NDIM];

// ---------------- fused quantization: blocks [0,NDIM) = weight rows, [NDIM,NDIM+MDIM) = activation rows ----------------
__global__ void __launch_bounds__(128) quant_fused_kernel(const float* __restrict__ w,
                                                          const float* __restrict__ x) {
    __shared__ float s0[4];
    __shared__ float s1[4];
    __shared__ int   si[4];
    const int t = threadIdx.x;

    if (blockIdx.x < NDIM) {
        // ---- weight row: symmetric int8 ----
        const int n = blockIdx.x;
        const float4* row = reinterpret_cast<const float4*>(w + (size_t)n * KDIM);
        float4 v[8];
        float am = 0.f;
#pragma unroll
        for (int i = 0; i < 8; i++) {
            v[i] = row[t + i * 128];
            am = fmaxf(am, fmaxf(fmaxf(fabsf(v[i].x), fabsf(v[i].y)),
                                 fmaxf(fabsf(v[i].z), fabsf(v[i].w))));
        }
#pragma unroll
        for (int o = 16; o > 0; o >>= 1) am = fmaxf(am, __shfl_xor_sync(0xffffffffu, am, o));
        if ((t & 31) == 0) s0[t >> 5] = am;
        __syncthreads();
        am = fmaxf(fmaxf(s0[0], s0[1]), fmaxf(s0[2], s0[3]));
        const float scale = (am > 0.f) ? (am / 127.0f) : 1.0f;

        char4* out = reinterpret_cast<char4*>(g_Wq + (size_t)n * KDIM);
        int ssum = 0;
#pragma unroll
        for (int i = 0; i < 8; i++) {
            int qx = (int)fminf(fmaxf(rintf(v[i].x / scale), -127.f), 127.f);
            int qy = (int)fminf(fmaxf(rintf(v[i].y / scale), -127.f), 127.f);
            int qz = (int)fminf(fmaxf(rintf(v[i].z / scale), -127.f), 127.f);
            int qw = (int)fminf(fmaxf(rintf(v[i].w / scale), -127.f), 127.f);
            ssum += qx + qy + qz + qw;
            out[t + i * 128] = make_char4((char)qx, (char)qy, (char)qz, (char)qw);
        }
#pragma unroll
        for (int o = 16; o > 0; o >>= 1) ssum += __shfl_xor_sync(0xffffffffu, ssum, o);
        if ((t & 31) == 0) si[t >> 5] = ssum;
        __syncthreads();
        if (t == 0) {
            g_sw[n]  = scale;
            g_rws[n] = si[0] + si[1] + si[2] + si[3];
        }
    } else {
        // ---- activation row: asymmetric uint8, stored as (q - 128) s8 ----
        const int m = blockIdx.x - NDIM;
        const float4* row = reinterpret_cast<const float4*>(x + (size_t)m * KDIM);
        float4 v[8];
        float mn = 3.4e38f, mx = -3.4e38f;
#pragma unroll
        for (int i = 0; i < 8; i++) {
            v[i] = row[t + i * 128];
            mn = fminf(mn, fminf(fminf(v[i].x, v[i].y), fminf(v[i].z, v[i].w)));
            mx = fmaxf(mx, fmaxf(fmaxf(v[i].x, v[i].y), fmaxf(v[i].z, v[i].w)));
        }
#pragma unroll
        for (int o = 16; o > 0; o >>= 1) {
            mn = fminf(mn, __shfl_xor_sync(0xffffffffu, mn, o));
            mx = fmaxf(mx, __shfl_xor_sync(0xffffffffu, mx, o));
        }
        if ((t & 31) == 0) { s0[t >> 5] = mn; s1[t >> 5] = mx; }
        __syncthreads();
        mn = fminf(fminf(s0[0], s0[1]), fminf(s0[2], s0[3]));
        mx = fmaxf(fmaxf(s1[0], s1[1]), fmaxf(s1[2], s1[3]));
        const float rng   = mx - mn;
        const float scale = (rng > 0.f) ? (rng / 255.0f) : 1.0f;
        const float zpf   = rintf((-mn) / scale);

        char4* out = reinterpret_cast<char4*>(g_Xq + (size_t)m * KDIM);
#pragma unroll
        for (int i = 0; i < 8; i++) {
            int qx = (int)fminf(fmaxf(rintf(v[i].x / scale) + zpf, 0.f), 255.f);
            int qy = (int)fminf(fmaxf(rintf(v[i].y / scale) + zpf, 0.f), 255.f);
            int qz = (int)fminf(fmaxf(rintf(v[i].z / scale) + zpf, 0.f), 255.f);
            int qw = (int)fminf(fmaxf(rintf(v[i].w / scale) + zpf, 0.f), 255.f);
            out[t + i * 128] = make_char4((char)(qx - 128), (char)(qy - 128),
                                          (char)(qz - 128), (char)(qw - 128));
        }
        if (t == 0) { g_sa[m] = scale; g_zp[m] = (int)zpf; }
    }
}

// ---------------- int8 GEMM: s8 x s8 -> s32, mma.sync m16n8k32 ----------------
// CTA 128x128, BK=128/stage, 3-stage cp.async ring, 4 warps, warp tile 64x64.
#define BM 128
#define BN 128
#define BKB 128
#define NSTG 3
#define NKT (KDIM / BKB)                         // 32 stages
#define STG_BYTES ((BM + BN) * BKB)              // 32768
#define SCALE_OFF (NSTG * STG_BYTES)             // 98304
#define DSMEM_BYTES (SCALE_OFF + 2560 + 1024)    // 101888

#define CP_ASYNC16(dst, src) \
    asm volatile("cp.async.cg.shared.global [%0], [%1], 16;\n" \
                 :: "r"(dst), "l"(__cvta_generic_to_global(src)))

#define LDSM_X4(R0, R1, R2, R3, A) \
    asm volatile("ldmatrix.sync.aligned.m8n8.x4.shared.b16 {%0,%1,%2,%3}, [%4];\n" \
                 : "=r"(R0), "=r"(R1), "=r"(R2), "=r"(R3) : "r"(A))

#define MMA_S8S8(C0, C1, C2, C3, A0, A1, A2, A3, B0, B1)               \
    asm volatile("mma.sync.aligned.m16n8k32.row.col.s32.s8.s8.s32 "    \
                 "{%0,%1,%2,%3}, {%4,%5,%6,%7}, {%8,%9}, {%0,%1,%2,%3};\n" \
                 : "+r"(C0), "+r"(C1), "+r"(C2), "+r"(C3)              \
                 : "r"(A0), "r"(A1), "r"(A2), "r"(A3), "r"(B0), "r"(B1))

extern __shared__ uint8_t dsm_raw[];

__device__ __forceinline__ void load_stage(uint32_t dstA, uint32_t dstB,
                                           const uint8_t* pA, const uint8_t* pB, int ko) {
#pragma unroll
    for (int i = 0; i < 8; i++)
        CP_ASYNC16(dstA + i * 2048, pA + (size_t)i * 16 * KDIM + ko);
#pragma unroll
    for (int i = 0; i < 8; i++)
        CP_ASYNC16(dstB + i * 2048, pB + (size_t)i * 16 * KDIM + ko);
    asm volatile("cp.async.commit_group;\n" ::: "memory");
}

__global__ void __launch_bounds__(128, 2) gemm_kernel(const float* __restrict__ bias,
                                                      float* __restrict__ out) {
    const int t    = threadIdx.x;
    const int warp = t >> 5, lane = t & 31;
    const int m0   = blockIdx.y * BM;
    const int n0   = blockIdx.x * BN;

    const uint32_t raw   = (uint32_t)__cvta_generic_to_shared(dsm_raw);
    const uint32_t sbase = (raw + 1023u) & ~1023u;
    uint8_t* sb_g = dsm_raw + (sbase - raw);

    float* sSa   = (float*)(sb_g + SCALE_OFF);
    int*   sZc   = (int*)  (sb_g + SCALE_OFF + 512);
    float* sSw   = (float*)(sb_g + SCALE_OFF + 1024);
    int*   sRw   = (int*)  (sb_g + SCALE_OFF + 1536);
    float* sBias = (float*)(sb_g + SCALE_OFF + 2048);

    sSa[t]   = g_sa[m0 + t];
    sZc[t]   = 128 - g_zp[m0 + t];   // acc_true = acc_s8s8 + (128 - zp) * rowsumW
    sSw[t]   = g_sw[n0 + t];
    sRw[t]   = g_rws[n0 + t];
    sBias[t] = bias[n0 + t];

    // ---- loader mapping: thread handles rows {16i + tr}, 16B chunk c, fixed swizzle ----
    const int tr = t >> 3, c = t & 7;                 // tr in 0..15, c in 0..7
    const uint32_t swc = (uint32_t)((c ^ (tr & 7)) << 4);
    const uint8_t* pA = (const uint8_t*)g_Xq + (size_t)(m0 + tr) * KDIM + c * 16;
    const uint8_t* pB = (const uint8_t*)g_Wq + (size_t)(n0 + tr) * KDIM + c * 16;
    const uint32_t ldA = tr * BKB + swc;              // offset within stage A region
    const uint32_t ldB = BM * BKB + tr * BKB + swc;   // offset within stage B region

    // ---- fragment addressing ----
    const int wm = warp >> 1, wn = warp & 1;          // warp tile 64x64
    const int aRow = wm * 64 + (lane & 15);
    const int aCh  = (lane >> 4) & 1;
    const int bRow = wn * 64 + (lane & 7) + ((lane >> 4) & 1) * 8;
    const int bCh  = (lane >> 3) & 1;
    const int l7   = lane & 7;

    int acc[4][8][4];
#pragma unroll
    for (int mi = 0; mi < 4; mi++)
#pragma unroll
        for (int ni = 0; ni < 8; ni++)
#pragma unroll
            for (int r = 0; r < 4; r++) acc[mi][ni][r] = 0;

    // prologue: stages 0,1
    load_stage(sbase + 0 * STG_BYTES + ldA, sbase + 0 * STG_BYTES + ldB, pA, pB, 0);
    load_stage(sbase + 1 * STG_BYTES + ldA, sbase + 1 * STG_BYTES + ldB, pA, pB, BKB);

    int slot = 0, lslot = 2;
#pragma unroll 1
    for (int stg = 0; stg < NKT; stg++) {
        if (stg + 2 < NKT) {
            load_stage(sbase + lslot * STG_BYTES + ldA, sbase + lslot * STG_BYTES + ldB,
                       pA, pB, (stg + 2) * BKB);
            lslot++; if (lslot == NSTG) lslot = 0;
        } else {
            asm volatile("cp.async.commit_group;\n" ::: "memory");
        }
        asm volatile("cp.async.wait_group 2;\n" ::: "memory");
        __syncthreads();

        const uint32_t sa = sbase + slot * STG_BYTES;
        const uint32_t sb = sa + BM * BKB;
#pragma unroll
        for (int ks = 0; ks < 4; ks++) {
            uint32_t a[4][4], bq[4][4];
            const uint32_t achu = (uint32_t)(((ks * 2 + aCh) ^ l7) << 4);
            const uint32_t bchu = (uint32_t)(((ks * 2 + bCh) ^ l7) << 4);
#pragma unroll
            for (int mi = 0; mi < 4; mi++) {
                const uint32_t ad = sa + (uint32_t)(aRow + mi * 16) * BKB + achu;
                LDSM_X4(a[mi][0], a[mi][1], a[mi][2], a[mi][3], ad);
            }
#pragma unroll
            for (int nj = 0; nj < 4; nj++) {
                const uint32_t ad = sb + (uint32_t)(bRow + nj * 16) * BKB + bchu;
                LDSM_X4(bq[nj][0], bq[nj][1], bq[nj][2], bq[nj][3], ad);
            }
#pragma unroll
            for (int mi = 0; mi < 4; mi++)
#pragma unroll
                for (int ni = 0; ni < 8; ni++) {
                    MMA_S8S8(acc[mi][ni][0], acc[mi][ni][1], acc[mi][ni][2], acc[mi][ni][3],
                             a[mi][0], a[mi][1], a[mi][2], a[mi][3],
                             bq[ni >> 1][(ni & 1) * 2], bq[ni >> 1][(ni & 1) * 2 + 1]);
                }
        }
        __syncthreads();
        slot++; if (slot == NSTG) slot = 0;
    }

    // ---- epilogue: shift + zero-point correction (exact int32) + dequant + bias ----
    const int rBase = wm * 64 + (lane >> 2);
    const int cBase = wn * 64 + (lane & 3) * 2;
#pragma unroll
    for (int mi = 0; mi < 4; mi++) {
        const int r0 = rBase + mi * 16;
        const int r1 = r0 + 8;
        const float sa0 = sSa[r0], sa1 = sSa[r1];
        const int   zc0 = sZc[r0], zc1 = sZc[r1];
        float* o0 = out + (size_t)(m0 + r0) * NDIM + n0;
        float* o1 = out + (size_t)(m0 + r1) * NDIM + n0;
#pragma unroll
        for (int ni = 0; ni < 8; ni++) {
            const int cc = cBase + ni * 8;
            const float sw0 = sSw[cc], sw1 = sSw[cc + 1];
            const int   rw0 = sRw[cc], rw1 = sRw[cc + 1];
            const float bb0 = sBias[cc], bb1 = sBias[cc + 1];
            float2 y0, y1;
            y0.x = (float)(acc[mi][ni][0] + zc0 * rw0) * (sa0 * sw0) + bb0;
            y0.y = (float)(acc[mi][ni][1] + zc0 * rw1) * (sa0 * sw1) + bb1;
            y1.x = (float)(acc[mi][ni][2] + zc1 * rw0) * (sa1 * sw0) + bb0;
            y1.y = (float)(acc[mi][ni][3] + zc1 * rw1) * (sa1 * sw1) + bb1;
            *reinterpret_cast<float2*>(o0 + cc) = y0;
            *reinterpret_cast<float2*>(o1 + cc) = y1;
        }
    }
}

// ---------------- launch ----------------
extern "C" void kernel_launch(void* const* d_in, const int* in_sizes, int n_in,
                              void* d_out, int out_size) {
    (void)in_sizes; (void)n_in; (void)out_size;
    const float* x    = (const float*)d_in[0];
    const float* w    = (const float*)d_in[1];
    const float* bias = (const float*)d_in[2];
    float* out = (float*)d_out;

    cudaFuncSetAttribute(gemm_kernel,
                         cudaFuncAttributeMaxDynamicSharedMemorySize, DSMEM_BYTES);

    quant_fused_kernel<<<NDIM + MDIM, 128>>>(w, x);
    dim3 grid(NDIM / BN, MDIM / BM);
    gemm_kernel<<<grid, 128, DSMEM_BYTES>>>(bias, out);
}

// round 12
// speedup vs baseline: 1.0912x; 1.0883x over previous
#include <cuda_runtime.h>
#include <cstdint>

#define MDIM 8192
#define NDIM 4096
#define KDIM 4096

// ---------------- scratch (device globals; no allocation allowed) ----------------
__device__ __align__(16) int8_t g_Xq[(size_t)MDIM * KDIM]; // 32 MB, stores (Xq - 128) as s8
__device__ __align__(16) int8_t g_Wq[(size_t)NDIM * KDIM]; // 16 MB
__device__ float g_sa[MDIM];
__device__ int   g_zp[MDIM];
__device__ float g_sw[NDIM];
__device__ int   g_rws[NDIM];

// ---------------- fused quantization (R9 proven) ----------------
__global__ void __launch_bounds__(128) quant_fused_kernel(const float* __restrict__ w,
                                                          const float* __restrict__ x) {
    __shared__ float s0[4];
    __shared__ float s1[4];
    __shared__ int   si[4];
    const int t = threadIdx.x;

    if (blockIdx.x < NDIM) {
        const int n = blockIdx.x;
        const float4* row = reinterpret_cast<const float4*>(w + (size_t)n * KDIM);
        float4 v[8];
        float am = 0.f;
#pragma unroll
        for (int i = 0; i < 8; i++) {
            v[i] = row[t + i * 128];
            am = fmaxf(am, fmaxf(fmaxf(fabsf(v[i].x), fabsf(v[i].y)),
                                 fmaxf(fabsf(v[i].z), fabsf(v[i].w))));
        }
#pragma unroll
        for (int o = 16; o > 0; o >>= 1) am = fmaxf(am, __shfl_xor_sync(0xffffffffu, am, o));
        if ((t & 31) == 0) s0[t >> 5] = am;
        __syncthreads();
        am = fmaxf(fmaxf(s0[0], s0[1]), fmaxf(s0[2], s0[3]));
        const float scale = (am > 0.f) ? (am / 127.0f) : 1.0f;

        char4* out = reinterpret_cast<char4*>(g_Wq + (size_t)n * KDIM);
        int ssum = 0;
#pragma unroll
        for (int i = 0; i < 8; i++) {
            int qx = (int)fminf(fmaxf(rintf(v[i].x / scale), -127.f), 127.f);
            int qy = (int)fminf(fmaxf(rintf(v[i].y / scale), -127.f), 127.f);
            int qz = (int)fminf(fmaxf(rintf(v[i].z / scale), -127.f), 127.f);
            int qw = (int)fminf(fmaxf(rintf(v[i].w / scale), -127.f), 127.f);
            ssum += qx + qy + qz + qw;
            out[t + i * 128] = make_char4((char)qx, (char)qy, (char)qz, (char)qw);
        }
#pragma unroll
        for (int o = 16; o > 0; o >>= 1) ssum += __shfl_xor_sync(0xffffffffu, ssum, o);
        if ((t & 31) == 0) si[t >> 5] = ssum;
        __syncthreads();
        if (t == 0) {
            g_sw[n]  = scale;
            g_rws[n] = si[0] + si[1] + si[2] + si[3];
        }
    } else {
        const int m = blockIdx.x - NDIM;
        const float4* row = reinterpret_cast<const float4*>(x + (size_t)m * KDIM);
        float4 v[8];
        float mn = 3.4e38f, mx = -3.4e38f;
#pragma unroll
        for (int i = 0; i < 8; i++) {
            v[i] = row[t + i * 128];
            mn = fminf(mn, fminf(fminf(v[i].x, v[i].y), fminf(v[i].z, v[i].w)));
            mx = fmaxf(mx, fmaxf(fmaxf(v[i].x, v[i].y), fmaxf(v[i].z, v[i].w)));
        }
#pragma unroll
        for (int o = 16; o > 0; o >>= 1) {
            mn = fminf(mn, __shfl_xor_sync(0xffffffffu, mn, o));
            mx = fmaxf(mx, __shfl_xor_sync(0xffffffffu, mx, o));
        }
        if ((t & 31) == 0) { s0[t >> 5] = mn; s1[t >> 5] = mx; }
        __syncthreads();
        mn = fminf(fminf(s0[0], s0[1]), fminf(s0[2], s0[3]));
        mx = fmaxf(fmaxf(s1[0], s1[1]), fmaxf(s1[2], s1[3]));
        const float rng   = mx - mn;
        const float scale = (rng > 0.f) ? (rng / 255.0f) : 1.0f;
        const float zpf   = rintf((-mn) / scale);

        char4* out = reinterpret_cast<char4*>(g_Xq + (size_t)m * KDIM);
#pragma unroll
        for (int i = 0; i < 8; i++) {
            int qx = (int)fminf(fmaxf(rintf(v[i].x / scale) + zpf, 0.f), 255.f);
            int qy = (int)fminf(fmaxf(rintf(v[i].y / scale) + zpf, 0.f), 255.f);
            int qz = (int)fminf(fmaxf(rintf(v[i].z / scale) + zpf, 0.f), 255.f);
            int qw = (int)fminf(fmaxf(rintf(v[i].w / scale) + zpf, 0.f), 255.f);
            out[t + i * 128] = make_char4((char)(qx - 128), (char)(qy - 128),
                                          (char)(qz - 128), (char)(qw - 128));
        }
        if (t == 0) { g_sa[m] = scale; g_zp[m] = (int)zpf; }
    }
}

// ---------------- hybrid int8 GEMM: tensor IMMA (K-chunks 0-2) + dp4a (chunk 3) ----------------
#define BM 128
#define BN 128
#define BKB 128
#define NSTG 4
#define NKT (KDIM / BKB)                         // 32 stages
#define STG_BYTES ((BM + BN) * BKB)              // 32768
#define SCALE_OFF (NSTG * STG_BYTES)             // 131072
#define DSMEM_BYTES (SCALE_OFF + 2560 + 1024)    // 134656

#define CP_ASYNC16(dst, src) \
    asm volatile("cp.async.cg.shared.global [%0], [%1], 16;\n" \
                 :: "r"(dst), "l"(__cvta_generic_to_global(src)))

#define LDSM_X4(R0, R1, R2, R3, A) \
    asm volatile("ldmatrix.sync.aligned.m8n8.x4.shared.b16 {%0,%1,%2,%3}, [%4];\n" \
                 : "=r"(R0), "=r"(R1), "=r"(R2), "=r"(R3) : "r"(A))

#define MMA_S8S8(C0, C1, C2, C3, A0, A1, A2, A3, B0, B1)               \
    asm volatile("mma.sync.aligned.m16n8k32.row.col.s32.s8.s8.s32 "    \
                 "{%0,%1,%2,%3}, {%4,%5,%6,%7}, {%8,%9}, {%0,%1,%2,%3};\n" \
                 : "+r"(C0), "+r"(C1), "+r"(C2), "+r"(C3)              \
                 : "r"(A0), "r"(A1), "r"(A2), "r"(A3), "r"(B0), "r"(B1))

#define LDS128I(v, addr) \
    asm volatile("ld.shared.v4.b32 {%0,%1,%2,%3}, [%4];" \
                 : "=r"((v).x), "=r"((v).y), "=r"((v).z), "=r"((v).w) : "r"(addr))

#define BARRIER() asm volatile("bar.sync 0;" ::: "memory")

extern __shared__ uint8_t dsm_raw[];

// per-thread share of one stage: 8 x 16B chunks (A rows i*32+tr for i<4, B for i>=4)
__device__ __forceinline__ void load_stage(uint32_t dst, const uint8_t* pA,
                                           const uint8_t* pB, int ko) {
#pragma unroll
    for (int i = 0; i < 4; i++)
        CP_ASYNC16(dst + i * 4096, pA + (size_t)i * 32 * KDIM + ko);
#pragma unroll
    for (int i = 0; i < 4; i++)
        CP_ASYNC16(dst + BM * BKB + i * 4096, pB + (size_t)i * 32 * KDIM + ko);
    asm volatile("cp.async.commit_group;\n" ::: "memory");
}

__global__ void __launch_bounds__(256, 1) gemm_kernel(const float* __restrict__ bias,
                                                      float* __restrict__ out) {
    const int t    = threadIdx.x;
    const int warp = t >> 5, lane = t & 31;
    const int m0   = blockIdx.y * BM;
    const int n0   = blockIdx.x * BN;

    const uint32_t raw   = (uint32_t)__cvta_generic_to_shared(dsm_raw);
    const uint32_t sbase = (raw + 1023u) & ~1023u;
    uint8_t* sb_g = dsm_raw + (sbase - raw);

    float* sSa   = (float*)(sb_g + SCALE_OFF);
    int*   sZc   = (int*)  (sb_g + SCALE_OFF + 512);
    float* sSw   = (float*)(sb_g + SCALE_OFF + 1024);
    int*   sRw   = (int*)  (sb_g + SCALE_OFF + 1536);
    float* sBias = (float*)(sb_g + SCALE_OFF + 2048);
    int*   mbuf  = (int*)sb_g;   // merge buffer, reuses stage slots 0-1 after mainloop

    if (t < 128) {
        sSa[t]   = g_sa[m0 + t];
        sZc[t]   = 128 - g_zp[m0 + t];   // acc_true = acc_s8s8 + (128 - zp) * rowsumW
        sSw[t]   = g_sw[n0 + t];
        sRw[t]   = g_rws[n0 + t];
        sBias[t] = bias[n0 + t];
    }

    // ---- loader mapping (all 256 threads) ----
    const int tr = t >> 3, c = t & 7;                 // tr 0..31, c 0..7
    const uint32_t swc = (uint32_t)((c ^ (tr & 7)) << 4);
    const uint8_t* pA = (const uint8_t*)g_Xq + (size_t)(m0 + tr) * KDIM + c * 16;
    const uint8_t* pB = (const uint8_t*)g_Wq + (size_t)(n0 + tr) * KDIM + c * 16;
    const uint32_t ldo = (uint32_t)(tr * BKB) + swc;

    // prologue: stages 0..2
    load_stage(sbase + 0 * STG_BYTES + ldo, pA, pB, 0 * BKB);
    load_stage(sbase + 1 * STG_BYTES + ldo, pA, pB, 1 * BKB);
    load_stage(sbase + 2 * STG_BYTES + ldo, pA, pB, 2 * BKB);

    if (warp < 4) {
        // ================= tensor warps: K-chunks 0..2 of every stage =================
        const int wm = warp >> 1, wn = warp & 1;          // warp tile 64x64
        const int aRow = wm * 64 + (lane & 15);
        const int aCh  = (lane >> 4) & 1;
        const int bRow = wn * 64 + (lane & 7) + ((lane >> 4) & 1) * 8;
        const int bCh  = (lane >> 3) & 1;
        const int l7   = lane & 7;

        int acc[4][8][4];
#pragma unroll
        for (int mi = 0; mi < 4; mi++)
#pragma unroll
            for (int ni = 0; ni < 8; ni++)
#pragma unroll
                for (int r = 0; r < 4; r++) acc[mi][ni][r] = 0;

#pragma unroll 1
        for (int stg = 0; stg < NKT; stg++) {
            if (stg + 3 < NKT)
                load_stage(sbase + ((stg + 3) & 3) * STG_BYTES + ldo, pA, pB, (stg + 3) * BKB);
            else
                asm volatile("cp.async.commit_group;\n" ::: "memory");
            asm volatile("cp.async.wait_group 3;\n" ::: "memory");
            BARRIER();

            const uint32_t sa = sbase + (stg & 3) * STG_BYTES;
            const uint32_t sb = sa + BM * BKB;
#pragma unroll
            for (int ks = 0; ks < 3; ks++) {
                uint32_t a[4][4], bq[4][4];
                const uint32_t achu = (uint32_t)(((ks * 2 + aCh) ^ l7) << 4);
                const uint32_t bchu = (uint32_t)(((ks * 2 + bCh) ^ l7) << 4);
#pragma unroll
                for (int mi = 0; mi < 4; mi++) {
                    const uint32_t ad = sa + (uint32_t)(aRow + mi * 16) * BKB + achu;
                    LDSM_X4(a[mi][0], a[mi][1], a[mi][2], a[mi][3], ad);
                }
#pragma unroll
                for (int nj = 0; nj < 4; nj++) {
                    const uint32_t ad = sb + (uint32_t)(bRow + nj * 16) * BKB + bchu;
                    LDSM_X4(bq[nj][0], bq[nj][1], bq[nj][2], bq[nj][3], ad);
                }
#pragma unroll
                for (int mi = 0; mi < 4; mi++)
#pragma unroll
                    for (int ni = 0; ni < 8; ni++) {
                        MMA_S8S8(acc[mi][ni][0], acc[mi][ni][1], acc[mi][ni][2], acc[mi][ni][3],
                                 a[mi][0], a[mi][1], a[mi][2], a[mi][3],
                                 bq[ni >> 1][(ni & 1) * 2], bq[ni >> 1][(ni & 1) * 2 + 1]);
                    }
            }
            BARRIER();
        }

        __syncthreads();   // dp4a warps have written mbuf

        // ---- epilogue: add dp4a partials + zero-point correction + dequant + bias ----
        const int rBase = wm * 64 + (lane >> 2);
        const int cBase = wn * 64 + (lane & 3) * 2;
#pragma unroll
        for (int mi = 0; mi < 4; mi++) {
            const int r0 = rBase + mi * 16;
            const int r1 = r0 + 8;
            const float sa0 = sSa[r0], sa1 = sSa[r1];
            const int   zc0 = sZc[r0], zc1 = sZc[r1];
            float* o0 = out + (size_t)(m0 + r0) * NDIM + n0;
            float* o1 = out + (size_t)(m0 + r1) * NDIM + n0;
#pragma unroll
            for (int ni = 0; ni < 8; ni++) {
                const int cc = cBase + ni * 8;
                const int2 p0 = *reinterpret_cast<const int2*>(&mbuf[r0 * BN + cc]);
                const int2 p1 = *reinterpret_cast<const int2*>(&mbuf[r1 * BN + cc]);
                const float sw0 = sSw[cc], sw1 = sSw[cc + 1];
                const int   rw0 = sRw[cc], rw1 = sRw[cc + 1];
                const float bb0 = sBias[cc], bb1 = sBias[cc + 1];
                float2 y0, y1;
                y0.x = (float)(acc[mi][ni][0] + p0.x + zc0 * rw0) * (sa0 * sw0) + bb0;
                y0.y = (float)(acc[mi][ni][1] + p0.y + zc0 * rw1) * (sa0 * sw1) + bb1;
                y1.x = (float)(acc[mi][ni][2] + p1.x + zc1 * rw0) * (sa1 * sw0) + bb0;
                y1.y = (float)(acc[mi][ni][3] + p1.y + zc1 * rw1) * (sa1 * sw1) + bb1;
                *reinterpret_cast<float2*>(o0 + cc) = y0;
                *reinterpret_cast<float2*>(o1 + cc) = y1;
            }
        }
    } else {
        // ================= dp4a warps: K-chunk 3 (bytes 96..127) of every stage =================
        const int dw = warp - 4;
        const int qm = dw >> 1, qn = dw & 1;              // 64x64 quadrant
        const int lm = lane & 7, ln = lane >> 3;          // lm 0..7 (rows), ln 0..3 (cols)
        const int rowbase = qm * 64 + lm * 8;
        const int colbase = qn * 64 + ln * 16;

        // rotated offsets: slot i holds logical row rowbase + ((i+lm)&7); conflict-free phases
        uint32_t aoff[8], boff[16];
#pragma unroll
        for (int i = 0; i < 8; i++) {
            const int rr = (i + lm) & 7;
            aoff[i] = (uint32_t)((rowbase + rr) * BKB + ((6 ^ rr) << 4));
        }
#pragma unroll
        for (int j = 0; j < 16; j++) {
            const int cx   = (j + 2 * ln) & 15;
            const int crow = colbase + cx;
            boff[j] = (uint32_t)(BM * BKB + crow * BKB + ((6 ^ (crow & 7)) << 4));
        }

        int acc[8][16];
#pragma unroll
        for (int i = 0; i < 8; i++)
#pragma unroll
            for (int j = 0; j < 16; j++) acc[i][j] = 0;

#pragma unroll 1
        for (int stg = 0; stg < NKT; stg++) {
            if (stg + 3 < NKT)
                load_stage(sbase + ((stg + 3) & 3) * STG_BYTES + ldo, pA, pB, (stg + 3) * BKB);
            else
                asm volatile("cp.async.commit_group;\n" ::: "memory");
            asm volatile("cp.async.wait_group 3;\n" ::: "memory");
            BARRIER();

            const uint32_t sa = sbase + (stg & 3) * STG_BYTES;
#pragma unroll
            for (int ch = 0; ch < 2; ch++) {              // 16B sub-chunks 6,7 (xor 16 flips 6<->7)
                const uint32_t xr = (uint32_t)(ch << 4);
                uint4 av[8];
#pragma unroll
                for (int i = 0; i < 8; i++) LDS128I(av[i], sa + (aoff[i] ^ xr));
#pragma unroll
                for (int jh = 0; jh < 2; jh++) {
                    uint4 bv[8];
#pragma unroll
                    for (int j = 0; j < 8; j++) LDS128I(bv[j], sa + (boff[jh * 8 + j] ^ xr));
#pragma unroll
                    for (int i = 0; i < 8; i++)
#pragma unroll
                        for (int j = 0; j < 8; j++) {
                            int* ap = &acc[i][jh * 8 + j];
                            *ap = __dp4a((int)av[i].x, (int)bv[j].x, *ap);
                            *ap = __dp4a((int)av[i].y, (int)bv[j].y, *ap);
                            *ap = __dp4a((int)av[i].z, (int)bv[j].z, *ap);
                            *ap = __dp4a((int)av[i].w, (int)bv[j].w, *ap);
                        }
                }
            }
            BARRIER();
        }

        // de-rotate and publish partials to merge buffer (stage slots 0-1, now dead)
#pragma unroll
        for (int i = 0; i < 8; i++) {
            const int r = rowbase + ((i + lm) & 7);
#pragma unroll
            for (int j = 0; j < 16; j++) {
                const int cfull = colbase + ((j + 2 * ln) & 15);
                mbuf[r * BN + cfull] = acc[i][j];
            }
        }
        __syncthreads();
    }
}

// ---------------- launch ----------------
extern "C" void kernel_launch(void* const* d_in, const int* in_sizes, int n_in,
                              void* d_out, int out_size) {
    (void)in_sizes; (void)n_in; (void)out_size;
    const float* x    = (const float*)d_in[0];
    const float* w    = (const float*)d_in[1];
    const float* bias = (const float*)d_in[2];
    float* out = (float*)d_out;

    cudaFuncSetAttribute(gemm_kernel,
                         cudaFuncAttributeMaxDynamicSharedMemorySize, DSMEM_BYTES);

    quant_fused_kernel<<<NDIM + MDIM, 128>>>(w, x);
    dim3 grid(NDIM / BN, MDIM / BM);
    gemm_kernel<<<grid, 256, DSMEM_BYTES>>>(bias, out);
}

// round 13
// speedup vs baseline: 1.1327x; 1.0380x over previous
#include <cuda_runtime.h>
#include <cstdint>

#define MDIM 8192
#define NDIM 4096
#define KDIM 4096

// ---------------- scratch (device globals; no allocation allowed) ----------------
__device__ __align__(16) int8_t g_Xq[(size_t)MDIM * KDIM]; // 32 MB, stores (Xq - 128) as s8
__device__ __align__(16) int8_t g_Wq[(size_t)NDIM * KDIM]; // 16 MB
__device__ float g_sa[MDIM];
__device__ int   g_zp[MDIM];
__device__ float g_sw[NDIM];
__device__ int   g_rws[NDIM];

// ---------------- fused quantization (proven) ----------------
__global__ void __launch_bounds__(128) quant_fused_kernel(const float* __restrict__ w,
                                                          const float* __restrict__ x) {
    __shared__ float s0[4];
    __shared__ float s1[4];
    __shared__ int   si[4];
    const int t = threadIdx.x;

    if (blockIdx.x < NDIM) {
        const int n = blockIdx.x;
        const float4* row = reinterpret_cast<const float4*>(w + (size_t)n * KDIM);
        float4 v[8];
        float am = 0.f;
#pragma unroll
        for (int i = 0; i < 8; i++) {
            v[i] = row[t + i * 128];
            am = fmaxf(am, fmaxf(fmaxf(fabsf(v[i].x), fabsf(v[i].y)),
                                 fmaxf(fabsf(v[i].z), fabsf(v[i].w))));
        }
#pragma unroll
        for (int o = 16; o > 0; o >>= 1) am = fmaxf(am, __shfl_xor_sync(0xffffffffu, am, o));
        if ((t & 31) == 0) s0[t >> 5] = am;
        __syncthreads();
        am = fmaxf(fmaxf(s0[0], s0[1]), fmaxf(s0[2], s0[3]));
        const float scale = (am > 0.f) ? (am / 127.0f) : 1.0f;

        char4* out = reinterpret_cast<char4*>(g_Wq + (size_t)n * KDIM);
        int ssum = 0;
#pragma unroll
        for (int i = 0; i < 8; i++) {
            int qx = (int)fminf(fmaxf(rintf(v[i].x / scale), -127.f), 127.f);
            int qy = (int)fminf(fmaxf(rintf(v[i].y / scale), -127.f), 127.f);
            int qz = (int)fminf(fmaxf(rintf(v[i].z / scale), -127.f), 127.f);
            int qw = (int)fminf(fmaxf(rintf(v[i].w / scale), -127.f), 127.f);
            ssum += qx + qy + qz + qw;
            out[t + i * 128] = make_char4((char)qx, (char)qy, (char)qz, (char)qw);
        }
#pragma unroll
        for (int o = 16; o > 0; o >>= 1) ssum += __shfl_xor_sync(0xffffffffu, ssum, o);
        if ((t & 31) == 0) si[t >> 5] = ssum;
        __syncthreads();
        if (t == 0) {
            g_sw[n]  = scale;
            g_rws[n] = si[0] + si[1] + si[2] + si[3];
        }
    } else {
        const int m = blockIdx.x - NDIM;
        const float4* row = reinterpret_cast<const float4*>(x + (size_t)m * KDIM);
        float4 v[8];
        float mn = 3.4e38f, mx = -3.4e38f;
#pragma unroll
        for (int i = 0; i < 8; i++) {
            v[i] = row[t + i * 128];
            mn = fminf(mn, fminf(fminf(v[i].x, v[i].y), fminf(v[i].z, v[i].w)));
            mx = fmaxf(mx, fmaxf(fmaxf(v[i].x, v[i].y), fmaxf(v[i].z, v[i].w)));
        }
#pragma unroll
        for (int o = 16; o > 0; o >>= 1) {
            mn = fminf(mn, __shfl_xor_sync(0xffffffffu, mn, o));
            mx = fmaxf(mx, __shfl_xor_sync(0xffffffffu, mx, o));
        }
        if ((t & 31) == 0) { s0[t >> 5] = mn; s1[t >> 5] = mx; }
        __syncthreads();
        mn = fminf(fminf(s0[0], s0[1]), fminf(s0[2], s0[3]));
        mx = fmaxf(fmaxf(s1[0], s1[1]), fmaxf(s1[2], s1[3]));
        const float rng   = mx - mn;
        const float scale = (rng > 0.f) ? (rng / 255.0f) : 1.0f;
        const float zpf   = rintf((-mn) / scale);

        char4* out = reinterpret_cast<char4*>(g_Xq + (size_t)m * KDIM);
#pragma unroll
        for (int i = 0; i < 8; i++) {
            int qx = (int)fminf(fmaxf(rintf(v[i].x / scale) + zpf, 0.f), 255.f);
            int qy = (int)fminf(fmaxf(rintf(v[i].y / scale) + zpf, 0.f), 255.f);
            int qz = (int)fminf(fmaxf(rintf(v[i].z / scale) + zpf, 0.f), 255.f);
            int qw = (int)fminf(fmaxf(rintf(v[i].w / scale) + zpf, 0.f), 255.f);
            out[t + i * 128] = make_char4((char)(qx - 128), (char)(qy - 128),
                                          (char)(qz - 128), (char)(qw - 128));
        }
        if (t == 0) { g_sa[m] = scale; g_zp[m] = (int)zpf; }
    }
}

// ---------------- hybrid int8 GEMM: tensor IMMA + dp4a, 68.75:31.25 K-split ----------------
// Stage = 128 K-bytes. Normal stage: tensor ks 0-2 (96B), dp4a 16B-chunks 6,7 (32B).
// Every 4th stage (stg&3==3): tensor ks 0-1 (64B), dp4a chunks 4,5,6,7 (64B).
#define BM 128
#define BN 128
#define BKB 128
#define NSTG 4
#define NKT (KDIM / BKB)                         // 32 stages
#define STG_BYTES ((BM + BN) * BKB)              // 32768
#define SCALE_OFF (NSTG * STG_BYTES)             // 131072
#define DSMEM_BYTES (SCALE_OFF + 2560 + 1024)    // 134656

#define CP_ASYNC16(dst, src) \
    asm volatile("cp.async.cg.shared.global [%0], [%1], 16;\n" \
                 :: "r"(dst), "l"(__cvta_generic_to_global(src)))

#define LDSM_X4(R0, R1, R2, R3, A) \
    asm volatile("ldmatrix.sync.aligned.m8n8.x4.shared.b16 {%0,%1,%2,%3}, [%4];\n" \
                 : "=r"(R0), "=r"(R1), "=r"(R2), "=r"(R3) : "r"(A))

#define MMA_S8S8(C0, C1, C2, C3, A0, A1, A2, A3, B0, B1)               \
    asm volatile("mma.sync.aligned.m16n8k32.row.col.s32.s8.s8.s32 "    \
                 "{%0,%1,%2,%3}, {%4,%5,%6,%7}, {%8,%9}, {%0,%1,%2,%3};\n" \
                 : "+r"(C0), "+r"(C1), "+r"(C2), "+r"(C3)              \
                 : "r"(A0), "r"(A1), "r"(A2), "r"(A3), "r"(B0), "r"(B1))

#define LDS128I(v, addr) \
    asm volatile("ld.shared.v4.b32 {%0,%1,%2,%3}, [%4];" \
                 : "=r"((v).x), "=r"((v).y), "=r"((v).z), "=r"((v).w) : "r"(addr))

#define BARRIER() asm volatile("bar.sync 0;" ::: "memory")

extern __shared__ uint8_t dsm_raw[];

// per-thread share of one stage: 8 x 16B chunks (A rows i*32+tr for i<4, B for i>=4)
__device__ __forceinline__ void load_stage(uint32_t dst, const uint8_t* pA,
                                           const uint8_t* pB, int ko) {
#pragma unroll
    for (int i = 0; i < 4; i++)
        CP_ASYNC16(dst + i * 4096, pA + (size_t)i * 32 * KDIM + ko);
#pragma unroll
    for (int i = 0; i < 4; i++)
        CP_ASYNC16(dst + BM * BKB + i * 4096, pB + (size_t)i * 32 * KDIM + ko);
    asm volatile("cp.async.commit_group;\n" ::: "memory");
}

// one m16n8k32 K-step for tensor warps
#define TENSOR_KS(ks) {                                                              \
    uint32_t a[4][4], bq[4][4];                                                      \
    const uint32_t achu = (uint32_t)((((ks) * 2 + aCh) ^ l7) << 4);                  \
    const uint32_t bchu = (uint32_t)((((ks) * 2 + bCh) ^ l7) << 4);                  \
    _Pragma("unroll")                                                                \
    for (int mi = 0; mi < 4; mi++) {                                                 \
        const uint32_t ad = sa + (uint32_t)(aRow + mi * 16) * BKB + achu;            \
        LDSM_X4(a[mi][0], a[mi][1], a[mi][2], a[mi][3], ad);                         \
    }                                                                                \
    _Pragma("unroll")                                                                \
    for (int nj = 0; nj < 4; nj++) {                                                 \
        const uint32_t ad = sb + (uint32_t)(bRow + nj * 16) * BKB + bchu;            \
        LDSM_X4(bq[nj][0], bq[nj][1], bq[nj][2], bq[nj][3], ad);                     \
    }                                                                                \
    _Pragma("unroll")                                                                \
    for (int mi = 0; mi < 4; mi++)                                                   \
        _Pragma("unroll")                                                            \
        for (int ni = 0; ni < 8; ni++) {                                             \
            MMA_S8S8(acc[mi][ni][0], acc[mi][ni][1], acc[mi][ni][2], acc[mi][ni][3], \
                     a[mi][0], a[mi][1], a[mi][2], a[mi][3],                         \
                     bq[ni >> 1][(ni & 1) * 2], bq[ni >> 1][(ni & 1) * 2 + 1]);      \
        }                                                                            \
}

// one 16B logical chunk for dp4a warps; bv blocked by 4 to bound register pressure
#define DP4A_CHUNK(clog) {                                                           \
    const uint32_t xr = (uint32_t)((clog) << 4);                                     \
    uint4 av[8];                                                                     \
    _Pragma("unroll")                                                                \
    for (int i = 0; i < 8; i++) LDS128I(av[i], sa + (aoff[i] ^ xr));                 \
    _Pragma("unroll")                                                                \
    for (int jb = 0; jb < 4; jb++) {                                                 \
        uint4 bv[4];                                                                 \
        _Pragma("unroll")                                                            \
        for (int j2 = 0; j2 < 4; j2++)                                               \
            LDS128I(bv[j2], sa + (boff[jb * 4 + j2] ^ xr));                          \
        _Pragma("unroll")                                                            \
        for (int i = 0; i < 8; i++)                                                  \
            _Pragma("unroll")                                                        \
            for (int j2 = 0; j2 < 4; j2++) {                                         \
                int* ap = &acc[i][jb * 4 + j2];                                      \
                *ap = __dp4a((int)av[i].x, (int)bv[j2].x, *ap);                      \
                *ap = __dp4a((int)av[i].y, (int)bv[j2].y, *ap);                      \
                *ap = __dp4a((int)av[i].z, (int)bv[j2].z, *ap);                      \
                *ap = __dp4a((int)av[i].w, (int)bv[j2].w, *ap);                      \
            }                                                                        \
    }                                                                                \
}

__global__ void __launch_bounds__(256, 1) gemm_kernel(const float* __restrict__ bias,
                                                      float* __restrict__ out) {
    const int t    = threadIdx.x;
    const int warp = t >> 5, lane = t & 31;
    const int m0   = blockIdx.y * BM;
    const int n0   = blockIdx.x * BN;

    const uint32_t raw   = (uint32_t)__cvta_generic_to_shared(dsm_raw);
    const uint32_t sbase = (raw + 1023u) & ~1023u;
    uint8_t* sb_g = dsm_raw + (sbase - raw);

    float* sSa   = (float*)(sb_g + SCALE_OFF);
    int*   sZc   = (int*)  (sb_g + SCALE_OFF + 512);
    float* sSw   = (float*)(sb_g + SCALE_OFF + 1024);
    int*   sRw   = (int*)  (sb_g + SCALE_OFF + 1536);
    float* sBias = (float*)(sb_g + SCALE_OFF + 2048);
    int*   mbuf  = (int*)sb_g;   // merge buffer, reuses stage slots 0-1 after mainloop

    if (t < 128) {
        sSa[t]   = g_sa[m0 + t];
        sZc[t]   = 128 - g_zp[m0 + t];   // acc_true = acc_s8s8 + (128 - zp) * rowsumW
        sSw[t]   = g_sw[n0 + t];
        sRw[t]   = g_rws[n0 + t];
        sBias[t] = bias[n0 + t];
    }

    // ---- loader mapping (all 256 threads) ----
    const int tr = t >> 3, c = t & 7;
    const uint32_t swc = (uint32_t)((c ^ (tr & 7)) << 4);
    const uint8_t* pA = (const uint8_t*)g_Xq + (size_t)(m0 + tr) * KDIM + c * 16;
    const uint8_t* pB = (const uint8_t*)g_Wq + (size_t)(n0 + tr) * KDIM + c * 16;
    const uint32_t ldo = (uint32_t)(tr * BKB) + swc;

    // prologue: stages 0..2
    load_stage(sbase + 0 * STG_BYTES + ldo, pA, pB, 0 * BKB);
    load_stage(sbase + 1 * STG_BYTES + ldo, pA, pB, 1 * BKB);
    load_stage(sbase + 2 * STG_BYTES + ldo, pA, pB, 2 * BKB);

    if (warp < 4) {
        // ================= tensor warps =================
        const int wm = warp >> 1, wn = warp & 1;          // warp tile 64x64
        const int aRow = wm * 64 + (lane & 15);
        const int aCh  = (lane >> 4) & 1;
        const int bRow = wn * 64 + (lane & 7) + ((lane >> 4) & 1) * 8;
        const int bCh  = (lane >> 3) & 1;
        const int l7   = lane & 7;

        int acc[4][8][4];
#pragma unroll
        for (int mi = 0; mi < 4; mi++)
#pragma unroll
            for (int ni = 0; ni < 8; ni++)
#pragma unroll
                for (int r = 0; r < 4; r++) acc[mi][ni][r] = 0;

#pragma unroll 1
        for (int stg = 0; stg < NKT; stg++) {
            if (stg + 3 < NKT)
                load_stage(sbase + ((stg + 3) & 3) * STG_BYTES + ldo, pA, pB, (stg + 3) * BKB);
            else
                asm volatile("cp.async.commit_group;\n" ::: "memory");
            asm volatile("cp.async.wait_group 3;\n" ::: "memory");
            BARRIER();

            const uint32_t sa = sbase + (stg & 3) * STG_BYTES;
            const uint32_t sb = sa + BM * BKB;
            TENSOR_KS(0);
            TENSOR_KS(1);
            if ((stg & 3) != 3) TENSOR_KS(2);
            BARRIER();
        }

        __syncthreads();   // dp4a warps have written mbuf

        // ---- epilogue: add dp4a partials + zero-point correction + dequant + bias ----
        const int rBase = wm * 64 + (lane >> 2);
        const int cBase = wn * 64 + (lane & 3) * 2;
#pragma unroll
        for (int mi = 0; mi < 4; mi++) {
            const int r0 = rBase + mi * 16;
            const int r1 = r0 + 8;
            const float sa0 = sSa[r0], sa1 = sSa[r1];
            const int   zc0 = sZc[r0], zc1 = sZc[r1];
            float* o0 = out + (size_t)(m0 + r0) * NDIM + n0;
            float* o1 = out + (size_t)(m0 + r1) * NDIM + n0;
#pragma unroll
            for (int ni = 0; ni < 8; ni++) {
                const int cc = cBase + ni * 8;
                const int2 p0 = *reinterpret_cast<const int2*>(&mbuf[r0 * BN + cc]);
                const int2 p1 = *reinterpret_cast<const int2*>(&mbuf[r1 * BN + cc]);
                const float sw0 = sSw[cc], sw1 = sSw[cc + 1];
                const int   rw0 = sRw[cc], rw1 = sRw[cc + 1];
                const float bb0 = sBias[cc], bb1 = sBias[cc + 1];
                float2 y0, y1;
                y0.x = (float)(acc[mi][ni][0] + p0.x + zc0 * rw0) * (sa0 * sw0) + bb0;
                y0.y = (float)(acc[mi][ni][1] + p0.y + zc0 * rw1) * (sa0 * sw1) + bb1;
                y1.x = (float)(acc[mi][ni][2] + p1.x + zc1 * rw0) * (sa1 * sw0) + bb0;
                y1.y = (float)(acc[mi][ni][3] + p1.y + zc1 * rw1) * (sa1 * sw1) + bb1;
                *reinterpret_cast<float2*>(o0 + cc) = y0;
                *reinterpret_cast<float2*>(o1 + cc) = y1;
            }
        }
    } else {
        // ================= dp4a warps =================
        const int dw = warp - 4;
        const int qm = dw >> 1, qn = dw & 1;              // 64x64 quadrant
        const int lm = lane & 7, ln = lane >> 3;
        const int rowbase = qm * 64 + lm * 8;
        const int colbase = qn * 64 + ln * 16;

        // rotated offsets: slot i holds logical row rowbase+((i+lm)&7); conflict-free phases.
        // aoff/boff carry the row's swizzle bits; XOR with (clog<<4) selects the chunk.
        uint32_t aoff[8], boff[16];
#pragma unroll
        for (int i = 0; i < 8; i++) {
            const int rr = (i + lm) & 7;
            aoff[i] = (uint32_t)((rowbase + rr) * BKB + (rr << 4));
        }
#pragma unroll
        for (int j = 0; j < 16; j++) {
            const int crow = colbase + ((j + 2 * ln) & 15);
            boff[j] = (uint32_t)(BM * BKB + crow * BKB + ((crow & 7) << 4));
        }

        int acc[8][16];
#pragma unroll
        for (int i = 0; i < 8; i++)
#pragma unroll
            for (int j = 0; j < 16; j++) acc[i][j] = 0;

#pragma unroll 1
        for (int stg = 0; stg < NKT; stg++) {
            if (stg + 3 < NKT)
                load_stage(sbase + ((stg + 3) & 3) * STG_BYTES + ldo, pA, pB, (stg + 3) * BKB);
            else
                asm volatile("cp.async.commit_group;\n" ::: "memory");
            asm volatile("cp.async.wait_group 3;\n" ::: "memory");
            BARRIER();

            const uint32_t sa = sbase + (stg & 3) * STG_BYTES;
            DP4A_CHUNK(6);
            DP4A_CHUNK(7);
            if ((stg & 3) == 3) { DP4A_CHUNK(4); DP4A_CHUNK(5); }
            BARRIER();
        }

        // de-rotate and publish partials to merge buffer (stage slots 0-1, now dead)
#pragma unroll
        for (int i = 0; i < 8; i++) {
            const int r = rowbase + ((i + lm) & 7);
#pragma unroll
            for (int j = 0; j < 16; j++) {
                const int cfull = colbase + ((j + 2 * ln) & 15);
                mbuf[r * BN + cfull] = acc[i][j];
            }
        }
        __syncthreads();
    }
}

// ---------------- launch ----------------
extern "C" void kernel_launch(void* const* d_in, const int* in_sizes, int n_in,
                              void* d_out, int out_size) {
    (void)in_sizes; (void)n_in; (void)out_size;
    const float* x    = (const float*)d_in[0];
    const float* w    = (const float*)d_in[1];
    const float* bias = (const float*)d_in[2];
    float* out = (float*)d_out;

    cudaFuncSetAttribute(gemm_kernel,
                         cudaFuncAttributeMaxDynamicSharedMemorySize, DSMEM_BYTES);

    quant_fused_kernel<<<NDIM + MDIM, 128>>>(w, x);
    dim3 grid(NDIM / BN, MDIM / BM);
    gemm_kernel<<<grid, 256, DSMEM_BYTES>>>(bias, out);
}

// round 16
// speedup vs baseline: 1.1422x; 1.0084x over previous
#include <cuda_runtime.h>
#include <cstdint>

#define MDIM 8192
#define NDIM 4096
#define KDIM 4096

// ---------------- scratch (device globals; no allocation allowed) ----------------
__device__ __align__(16) int8_t g_Xq[(size_t)MDIM * KDIM]; // 32 MB, stores (Xq - 128) as s8
__device__ __align__(16) int8_t g_Wq[(size_t)NDIM * KDIM]; // 16 MB
__device__ float g_sa[MDIM];
__device__ int   g_zp[MDIM];
__device__ float g_sw[NDIM];
__device__ int   g_rws[NDIM];

// ---------------- fused quantization (proven) ----------------
__global__ void __launch_bounds__(128) quant_fused_kernel(const float* __restrict__ w,
                                                          const float* __restrict__ x) {
    __shared__ float s0[4];
    __shared__ float s1[4];
    __shared__ int   si[4];
    const int t = threadIdx.x;

    if (blockIdx.x < NDIM) {
        const int n = blockIdx.x;
        const float4* row = reinterpret_cast<const float4*>(w + (size_t)n * KDIM);
        float4 v[8];
        float am = 0.f;
#pragma unroll
        for (int i = 0; i < 8; i++) {
            v[i] = row[t + i * 128];
            am = fmaxf(am, fmaxf(fmaxf(fabsf(v[i].x), fabsf(v[i].y)),
                                 fmaxf(fabsf(v[i].z), fabsf(v[i].w))));
        }
#pragma unroll
        for (int o = 16; o > 0; o >>= 1) am = fmaxf(am, __shfl_xor_sync(0xffffffffu, am, o));
        if ((t & 31) == 0) s0[t >> 5] = am;
        __syncthreads();
        am = fmaxf(fmaxf(s0[0], s0[1]), fmaxf(s0[2], s0[3]));
        const float scale = (am > 0.f) ? (am / 127.0f) : 1.0f;

        char4* out = reinterpret_cast<char4*>(g_Wq + (size_t)n * KDIM);
        int ssum = 0;
#pragma unroll
        for (int i = 0; i < 8; i++) {
            int qx = (int)fminf(fmaxf(rintf(v[i].x / scale), -127.f), 127.f);
            int qy = (int)fminf(fmaxf(rintf(v[i].y / scale), -127.f), 127.f);
            int qz = (int)fminf(fmaxf(rintf(v[i].z / scale), -127.f), 127.f);
            int qw = (int)fminf(fmaxf(rintf(v[i].w / scale), -127.f), 127.f);
            ssum += qx + qy + qz + qw;
            out[t + i * 128] = make_char4((char)qx, (char)qy, (char)qz, (char)qw);
        }
#pragma unroll
        for (int o = 16; o > 0; o >>= 1) ssum += __shfl_xor_sync(0xffffffffu, ssum, o);
        if ((t & 31) == 0) si[t >> 5] = ssum;
        __syncthreads();
        if (t == 0) {
            g_sw[n]  = scale;
            g_rws[n] = si[0] + si[1] + si[2] + si[3];
        }
    } else {
        const int m = blockIdx.x - NDIM;
        const float4* row = reinterpret_cast<const float4*>(x + (size_t)m * KDIM);
        float4 v[8];
        float mn = 3.4e38f, mx = -3.4e38f;
#pragma unroll
        for (int i = 0; i < 8; i++) {
            v[i] = row[t + i * 128];
            mn = fminf(mn, fminf(fminf(v[i].x, v[i].y), fminf(v[i].z, v[i].w)));
            mx = fmaxf(mx, fmaxf(fmaxf(v[i].x, v[i].y), fmaxf(v[i].z, v[i].w)));
        }
#pragma unroll
        for (int o = 16; o > 0; o >>= 1) {
            mn = fminf(mn, __shfl_xor_sync(0xffffffffu, mn, o));
            mx = fmaxf(mx, __shfl_xor_sync(0xffffffffu, mx, o));
        }
        if ((t & 31) == 0) { s0[t >> 5] = mn; s1[t >> 5] = mx; }
        __syncthreads();
        mn = fminf(fminf(s0[0], s0[1]), fminf(s0[2], s0[3]));
        mx = fmaxf(fmaxf(s1[0], s1[1]), fmaxf(s1[2], s1[3]));
        const float rng   = mx - mn;
        const float scale = (rng > 0.f) ? (rng / 255.0f) : 1.0f;
        const float zpf   = rintf((-mn) / scale);

        char4* out = reinterpret_cast<char4*>(g_Xq + (size_t)m * KDIM);
#pragma unroll
        for (int i = 0; i < 8; i++) {
            int qx = (int)fminf(fmaxf(rintf(v[i].x / scale) + zpf, 0.f), 255.f);
            int qy = (int)fminf(fmaxf(rintf(v[i].y / scale) + zpf, 0.f), 255.f);
            int qz = (int)fminf(fmaxf(rintf(v[i].z / scale) + zpf, 0.f), 255.f);
            int qw = (int)fminf(fmaxf(rintf(v[i].w / scale) + zpf, 0.f), 255.f);
            out[t + i * 128] = make_char4((char)(qx - 128), (char)(qy - 128),
                                          (char)(qz - 128), (char)(qw - 128));
        }
        if (t == 0) { g_sa[m] = scale; g_zp[m] = (int)zpf; }
    }
}

// ---------------- hybrid int8 GEMM: tensor IMMA + dp4a, 68.75:31.25 K-split ----------------
// Stage = 128 K-bytes. Normal stage: tensor ks 0-2 (96B), dp4a 16B-chunks 6,7 (32B).
// Every 4th stage (stg&3==3): tensor ks 0-1 (64B), dp4a chunks 4,5,6,7 (64B).
// 5-stage ring -> ONE barrier per stage (extra slot makes end-of-stage barrier provably
// unnecessary: all threads pass barrier s-1 only after finishing compute s-2, and the
// load issued at iteration s targets slot (s+3)%5 == (s-2)%5).
#define BM 128
#define BN 128
#define BKB 128
#define NSTG 5
#define NKT (KDIM / BKB)                         // 32 stages
#define STG_BYTES ((BM + BN) * BKB)              // 32768
#define SCALE_OFF (NSTG * STG_BYTES)             // 163840
#define DSMEM_BYTES (SCALE_OFF + 2560 + 1024)    // 167424
#define MBUF_OFF (2 * STG_BYTES)                 // merge buffer = slots 2,3 (last used stages 27/28)

#define CP_ASYNC16(dst, src) \
    asm volatile("cp.async.cg.shared.global [%0], [%1], 16;\n" \
                 :: "r"(dst), "l"(__cvta_generic_to_global(src)))

#define LDSM_X4(R0, R1, R2, R3, A) \
    asm volatile("ldmatrix.sync.aligned.m8n8.x4.shared.b16 {%0,%1,%2,%3}, [%4];\n" \
                 : "=r"(R0), "=r"(R1), "=r"(R2), "=r"(R3) : "r"(A))

#define MMA_S8S8(C0, C1, C2, C3, A0, A1, A2, A3, B0, B1)               \
    asm volatile("mma.sync.aligned.m16n8k32.row.col.s32.s8.s8.s32 "    \
                 "{%0,%1,%2,%3}, {%4,%5,%6,%7}, {%8,%9}, {%0,%1,%2,%3};\n" \
                 : "+r"(C0), "+r"(C1), "+r"(C2), "+r"(C3)              \
                 : "r"(A0), "r"(A1), "r"(A2), "r"(A3), "r"(B0), "r"(B1))

#define LDS128I(v, addr) \
    asm volatile("ld.shared.v4.b32 {%0,%1,%2,%3}, [%4];" \
                 : "=r"((v).x), "=r"((v).y), "=r"((v).z), "=r"((v).w) : "r"(addr))

#define BARRIER() asm volatile("bar.sync 0;" ::: "memory")

extern __shared__ uint8_t dsm_raw[];

// per-thread share of one stage: 8 x 16B chunks (A rows i*32+tr for i<4, B for i>=4)
__device__ __forceinline__ void load_stage(uint32_t dst, const uint8_t* pA,
                                           const uint8_t* pB, int ko) {
#pragma unroll
    for (int i = 0; i < 4; i++)
        CP_ASYNC16(dst + i * 4096, pA + (size_t)i * 32 * KDIM + ko);
#pragma unroll
    for (int i = 0; i < 4; i++)
        CP_ASYNC16(dst + BM * BKB + i * 4096, pB + (size_t)i * 32 * KDIM + ko);
    asm volatile("cp.async.commit_group;\n" ::: "memory");
}

// one m16n8k32 K-step for tensor warps
#define TENSOR_KS(ks) {                                                              \
    uint32_t a[4][4], bq[4][4];                                                      \
    const uint32_t achu = (uint32_t)((((ks) * 2 + aCh) ^ l7) << 4);                  \
    const uint32_t bchu = (uint32_t)((((ks) * 2 + bCh) ^ l7) << 4);                  \
    _Pragma("unroll")                                                                \
    for (int mi = 0; mi < 4; mi++) {                                                 \
        const uint32_t ad = sa + (uint32_t)(aRow + mi * 16) * BKB + achu;            \
        LDSM_X4(a[mi][0], a[mi][1], a[mi][2], a[mi][3], ad);                         \
    }                                                                                \
    _Pragma("unroll")                                                                \
    for (int nj = 0; nj < 4; nj++) {                                                 \
        const uint32_t ad = sb + (uint32_t)(bRow + nj * 16) * BKB + bchu;            \
        LDSM_X4(bq[nj][0], bq[nj][1], bq[nj][2], bq[nj][3], ad);                     \
    }                                                                                \
    _Pragma("unroll")                                                                \
    for (int mi = 0; mi < 4; mi++)                                                   \
        _Pragma("unroll")                                                            \
        for (int ni = 0; ni < 8; ni++) {                                             \
            MMA_S8S8(acc[mi][ni][0], acc[mi][ni][1], acc[mi][ni][2], acc[mi][ni][3], \
                     a[mi][0], a[mi][1], a[mi][2], a[mi][3],                         \
                     bq[ni >> 1][(ni & 1) * 2], bq[ni >> 1][(ni & 1) * 2 + 1]);      \
        }                                                                            \
}

// one 16B logical chunk for dp4a warps; row-halves (av[4]) + bv[4] blocks to
// bound the live register set (~205) and eliminate local-memory spills.
#define DP4A_CHUNK(clog) {                                                           \
    const uint32_t xr = (uint32_t)((clog) << 4);                                     \
    _Pragma("unroll")                                                                \
    for (int ih = 0; ih < 2; ih++) {                                                 \
        uint4 av[4];                                                                 \
        _Pragma("unroll")                                                            \
        for (int ii = 0; ii < 4; ii++)                                               \
            LDS128I(av[ii], sa + (aoff[ih * 4 + ii] ^ xr));                          \
        _Pragma("unroll")                                                            \
        for (int jb = 0; jb < 4; jb++) {                                             \
            uint4 bv[4];                                                             \
            _Pragma("unroll")                                                        \
            for (int j2 = 0; j2 < 4; j2++)                                           \
                LDS128I(bv[j2], sa + (boff[jb * 4 + j2] ^ xr));                      \
            _Pragma("unroll")                                                        \
            for (int ii = 0; ii < 4; ii++)                                           \
                _Pragma("unroll")                                                    \
                for (int j2 = 0; j2 < 4; j2++) {                                     \
                    int* ap = &acc[ih * 4 + ii][jb * 4 + j2];                        \
                    *ap = __dp4a((int)av[ii].x, (int)bv[j2].x, *ap);                 \
                    *ap = __dp4a((int)av[ii].y, (int)bv[j2].y, *ap);                 \
                    *ap = __dp4a((int)av[ii].z, (int)bv[j2].z, *ap);                 \
                    *ap = __dp4a((int)av[ii].w, (int)bv[j2].w, *ap);                 \
                }                                                                    \
        }                                                                            \
    }                                                                                \
}

__global__ void __launch_bounds__(256, 1) gemm_kernel(const float* __restrict__ bias,
                                                      float* __restrict__ out) {
    const int t    = threadIdx.x;
    const int warp = t >> 5, lane = t & 31;
    const int m0   = blockIdx.y * BM;
    const int n0   = blockIdx.x * BN;

    const uint32_t raw   = (uint32_t)__cvta_generic_to_shared(dsm_raw);
    const uint32_t sbase = (raw + 1023u) & ~1023u;
    uint8_t* sb_g = dsm_raw + (sbase - raw);

    float* sSa   = (float*)(sb_g + SCALE_OFF);
    int*   sZc   = (int*)  (sb_g + SCALE_OFF + 512);
    float* sSw   = (float*)(sb_g + SCALE_OFF + 1024);
    int*   sRw   = (int*)  (sb_g + SCALE_OFF + 1536);
    float* sBias = (float*)(sb_g + SCALE_OFF + 2048);
    int*   mbuf  = (int*)(sb_g + MBUF_OFF);  // slots 2,3: last ring use = stages 27/28

    if (t < 128) {
        sSa[t]   = g_sa[m0 + t];
        sZc[t]   = 128 - g_zp[m0 + t];   // acc_true = acc_s8s8 + (128 - zp) * rowsumW
        sSw[t]   = g_sw[n0 + t];
        sRw[t]   = g_rws[n0 + t];
        sBias[t] = bias[n0 + t];
    }

    // ---- loader mapping (all 256 threads) ----
    const int tr = t >> 3, c = t & 7;
    const uint32_t swc = (uint32_t)((c ^ (tr & 7)) << 4);
    const uint8_t* pA = (const uint8_t*)g_Xq + (size_t)(m0 + tr) * KDIM + c * 16;
    const uint8_t* pB = (const uint8_t*)g_Wq + (size_t)(n0 + tr) * KDIM + c * 16;
    const uint32_t ldo = (uint32_t)(tr * BKB) + swc;

    // prologue: stages 0..2
    load_stage(sbase + 0 * STG_BYTES + ldo, pA, pB, 0 * BKB);
    load_stage(sbase + 1 * STG_BYTES + ldo, pA, pB, 1 * BKB);
    load_stage(sbase + 2 * STG_BYTES + ldo, pA, pB, 2 * BKB);

    if (warp < 4) {
        // ================= tensor warps =================
        const int wm = warp >> 1, wn = warp & 1;          // warp tile 64x64
        const int aRow = wm * 64 + (lane & 15);
        const int aCh  = (lane >> 4) & 1;
        const int bRow = wn * 64 + (lane & 7) + ((lane >> 4) & 1) * 8;
        const int bCh  = (lane >> 3) & 1;
        const int l7   = lane & 7;

        int acc[4][8][4];
#pragma unroll
        for (int mi = 0; mi < 4; mi++)
#pragma unroll
            for (int ni = 0; ni < 8; ni++)
#pragma unroll
                for (int r = 0; r < 4; r++) acc[mi][ni][r] = 0;

        int slot = 0, lslot = 3;
#pragma unroll 1
        for (int stg = 0; stg < NKT; stg++) {
            if (stg + 3 < NKT) {
                load_stage(sbase + lslot * STG_BYTES + ldo, pA, pB, (stg + 3) * BKB);
                lslot++; if (lslot == NSTG) lslot = 0;
            } else {
                asm volatile("cp.async.commit_group;\n" ::: "memory");
            }
            asm volatile("cp.async.wait_group 3;\n" ::: "memory");
            BARRIER();

            const uint32_t sa = sbase + slot * STG_BYTES;
            const uint32_t sb = sa + BM * BKB;
            TENSOR_KS(0);
            TENSOR_KS(1);
            if ((stg & 3) != 3) TENSOR_KS(2);
            slot++; if (slot == NSTG) slot = 0;
        }

        __syncthreads();   // dp4a warps have written mbuf

        // ---- epilogue: add dp4a partials + zero-point correction + dequant + bias ----
        const int rBase = wm * 64 + (lane >> 2);
        const int cBase = wn * 64 + (lane & 3) * 2;
#pragma unroll
        for (int mi = 0; mi < 4; mi++) {
            const int r0 = rBase + mi * 16;
            const int r1 = r0 + 8;
            const float sa0 = sSa[r0], sa1 = sSa[r1];
            const int   zc0 = sZc[r0], zc1 = sZc[r1];
            float* o0 = out + (size_t)(m0 + r0) * NDIM + n0;
            float* o1 = out + (size_t)(m0 + r1) * NDIM + n0;
#pragma unroll
            for (int ni = 0; ni < 8; ni++) {
                const int cc = cBase + ni * 8;
                const int2 p0 = *reinterpret_cast<const int2*>(&mbuf[r0 * BN + cc]);
                const int2 p1 = *reinterpret_cast<const int2*>(&mbuf[r1 * BN + cc]);
                const float sw0 = sSw[cc], sw1 = sSw[cc + 1];
                const int   rw0 = sRw[cc], rw1 = sRw[cc + 1];
                const float bb0 = sBias[cc], bb1 = sBias[cc + 1];
                float2 y0, y1;
                y0.x = (float)(acc[mi][ni][0] + p0.x + zc0 * rw0) * (sa0 * sw0) + bb0;
                y0.y = (float)(acc[mi][ni][1] + p0.y + zc0 * rw1) * (sa0 * sw1) + bb1;
                y1.x = (float)(acc[mi][ni][2] + p1.x + zc1 * rw0) * (sa1 * sw0) + bb0;
                y1.y = (float)(acc[mi][ni][3] + p1.y + zc1 * rw1) * (sa1 * sw1) + bb1;
                *reinterpret_cast<float2*>(o0 + cc) = y0;
                *reinterpret_cast<float2*>(o1 + cc) = y1;
            }
        }
    } else {
        // ================= dp4a warps =================
        const int dw = warp - 4;
        const int qm = dw >> 1, qn = dw & 1;              // 64x64 quadrant
        const int lm = lane & 7, ln = lane >> 3;
        const int rowbase = qm * 64 + lm * 8;
        const int colbase = qn * 64 + ln * 16;

        // rotated offsets: slot i holds logical row rowbase+((i+lm)&7); conflict-free phases.
        // aoff/boff carry the row's swizzle bits; XOR with (clog<<4) selects the chunk.
        uint32_t aoff[8], boff[16];
#pragma unroll
        for (int i = 0; i < 8; i++) {
            const int rr = (i + lm) & 7;
            aoff[i] = (uint32_t)((rowbase + rr) * BKB + (rr << 4));
        }
#pragma unroll
        for (int j = 0; j < 16; j++) {
            const int crow = colbase + ((j + 2 * ln) & 15);
            boff[j] = (uint32_t)(BM * BKB + crow * BKB + ((crow & 7) << 4));
        }

        int acc[8][16];
#pragma unroll
        for (int i = 0; i < 8; i++)
#pragma unroll
            for (int j = 0; j < 16; j++) acc[i][j] = 0;

        int slot = 0, lslot = 3;
#pragma unroll 1
        for (int stg = 0; stg < NKT; stg++) {
            if (stg + 3 < NKT) {
                load_stage(sbase + lslot * STG_BYTES + ldo, pA, pB, (stg + 3) * BKB);
                lslot++; if (lslot == NSTG) lslot = 0;
            } else {
                asm volatile("cp.async.commit_group;\n" ::: "memory");
            }
            asm volatile("cp.async.wait_group 3;\n" ::: "memory");
            BARRIER();

            const uint32_t sa = sbase + slot * STG_BYTES;
            DP4A_CHUNK(6);
            DP4A_CHUNK(7);
            if ((stg & 3) == 3) { DP4A_CHUNK(4); DP4A_CHUNK(5); }
            slot++; if (slot == NSTG) slot = 0;
        }

        // de-rotate and publish partials to merge buffer (slots 2,3 of ring: last
        // ring use was stages 27/28, and all threads are past barrier 31 region safety)
#pragma unroll
        for (int i = 0; i < 8; i++) {
            const int r = rowbase + ((i + lm) & 7);
#pragma unroll
            for (int j = 0; j < 16; j++) {
                const int cfull = colbase + ((j + 2 * ln) & 15);
                mbuf[r * BN + cfull] = acc[i][j];
            }
        }
        __syncthreads();
    }
}

// ---------------- launch ----------------
extern "C" void kernel_launch(void* const* d_in, const int* in_sizes, int n_in,
                              void* d_out, int out_size) {
    (void)in_sizes; (void)n_in; (void)out_size;
    const float* x    = (const float*)d_in[0];
    const float* w    = (const float*)d_in[1];
    const float* bias = (const float*)d_in[2];
    float* out = (float*)d_out;

    cudaFuncSetAttribute(gemm_kernel,
                         cudaFuncAttributeMaxDynamicSharedMemorySize, DSMEM_BYTES);

    quant_fused_kernel<<<NDIM + MDIM, 128>>>(w, x);
    dim3 grid(NDIM / BN, MDIM / BM);
    gemm_kernel<<<grid, 256, DSMEM_BYTES>>>(bias, out);
}